// round 16
// baseline (speedup 1.0000x reference)
#include <cuda_runtime.h>
#include <cuda_bf16.h>
#include <cstdint>

// Retrace loss — persistent CTAs + TMA bulk-copy (cp.async.bulk 1D) staging.
// grid = 592 = 148 SM * 4 CTA (single wave). Per row, ONE thread issues 6 bulk
// copies (one per input array) of the row's contiguous 4112-byte window into a
// double-buffered smem stage; an mbarrier expect_tx ring tracks completion.
// row*1025 ≡ bid (mod 4)  =>  window alignment residue c = bid&3 constant per
// CTA; array shift s (Q:0, r:+1, others:+2) gives a per-CTA-constant smem word
// offset off = c+s, consumed with 2 conflict-free LDS.128 + uniform selects.
// Scan per row: serial compose 4 -> one warp suffix scan -> cross-warp combine
// (double-buffered totals, ONE __syncthreads, redundant per-thread compose).
// Completion: one arrival per CTA; wrap-around counter -> deterministic replays.
// Affine composition: (A1,B1) o (A2,B2) = (A1 + B1*A2, B1*B2).

#define S_STRIDE 1025
#define T_LEN    1024
#define NROWS    4096
#define GAMMA_F  0.99f
#define EPS_F    1e-10f
#define NTHREADS 256
#define GRID     592

#define NARR            6
#define SEG_COPY_BYTES  4112                       // 1028 words, mult of 16
#define SEG_ALLOC_WORDS 1032                       // 4128 B: pads chunk overreads
#define STAGE_WORDS     (NARR * SEG_ALLOC_WORDS)   // 6192 words / stage
#define SMEM_BYTES      (2 * STAGE_WORDS * 4)      // 49536 B dynamic smem

__device__ double   g_part[GRID];
__device__ unsigned g_cnt = 0;   // wraps at GRID-1 -> deterministic across replays

struct Aff { float a, b; };

__device__ __forceinline__ Aff comp(Aff f, Aff g) {
    Aff r;
    r.a = fmaf(f.b, g.a, f.a);
    r.b = f.b * g.b;
    return r;
}

__device__ __forceinline__ uint32_t smem_u32(const void* p) {
    return (uint32_t)__cvta_generic_to_shared(p);
}

__device__ __forceinline__ void mbar_init(uint32_t bar, uint32_t cnt) {
    asm volatile("mbarrier.init.shared.b64 [%0], %1;" :: "r"(bar), "r"(cnt) : "memory");
}

__device__ __forceinline__ void mbar_expect_tx(uint32_t bar, uint32_t bytes) {
    asm volatile("mbarrier.arrive.expect_tx.shared.b64 _, [%0], %1;"
                 :: "r"(bar), "r"(bytes) : "memory");
}

__device__ __forceinline__ void mbar_wait(uint32_t bar, uint32_t parity) {
    asm volatile(
        "{\n\t"
        ".reg .pred P1;\n\t"
        "WAIT_LOOP_%=:\n\t"
        "mbarrier.try_wait.parity.acquire.cta.shared::cta.b64 P1, [%0], %1, 0x989680;\n\t"
        "@P1 bra.uni WAIT_DONE_%=;\n\t"
        "bra.uni WAIT_LOOP_%=;\n\t"
        "WAIT_DONE_%=:\n\t"
        "}"
        :: "r"(bar), "r"(parity) : "memory");
}

__device__ __forceinline__ void bulk_copy(uint32_t dst_smem, const float* src,
                                          uint32_t bytes, uint32_t bar) {
    asm volatile(
        "cp.async.bulk.shared::cta.global.mbarrier::complete_tx::bytes [%0], [%1], %2, [%3];"
        :: "r"(dst_smem), "l"(src), "r"(bytes), "r"(bar) : "memory");
}

// Read words off+j0 .. off+j0+3 from a stage array (off uniform per CTA, 0..5).
__device__ __forceinline__ float4 lds_shift(const float* arr, int off, int j0) {
    const float4* p = reinterpret_cast<const float4*>(arr);
    const int q0 = (off + j0) >> 2;      // j0 mult of 4 -> m = off & 3
    const int m  = off & 3;
    const float4 lo = p[q0];             // stride-16B across lanes: conflict-free
    if (m == 0) return lo;
    const float4 hi = p[q0 + 1];
    float4 o;
    if (m == 1)      { o.x = lo.y; o.y = lo.z; o.z = lo.w; o.w = hi.x; }
    else if (m == 2) { o.x = lo.z; o.y = lo.w; o.z = hi.x; o.w = hi.y; }
    else             { o.x = lo.w; o.y = hi.x; o.z = hi.y; o.w = hi.z; }
    return o;
}

__global__ void __launch_bounds__(NTHREADS, 4)
retrace_kernel(const float* __restrict__ Q,
               const float* __restrict__ eQ,
               const float* __restrict__ tQ,
               const float* __restrict__ r,
               const float* __restrict__ tp,
               const float* __restrict__ bp,
               float* __restrict__ out)
{
    extern __shared__ __align__(16) float smem[];
    __shared__ __align__(8) unsigned long long mbar[2];
    __shared__ float swA[2][8], swB[2][8];   // double-buffered warp totals
    __shared__ double ssum[8];
    __shared__ bool s_last;

    const int bid = blockIdx.x;
    const int t = threadIdx.x;
    const int lane = t & 31;
    const int w = t >> 5;
    const int seg = w * 128;
    const int j0 = seg + 4 * lane;      // this thread's first col
    const int c = bid & 3;              // window alignment residue (constant/CTA)

    const float* arrs[NARR] = { Q, r, eQ, tQ, tp, bp };
    const uint32_t smem_base = smem_u32(smem);
    const uint32_t bar_u[2] = { smem_u32(&mbar[0]), smem_u32(&mbar[1]) };

    if (t == 0) { mbar_init(bar_u[0], 1); mbar_init(bar_u[1], 1); }
    __syncthreads();

    // issue one row's 6 bulk copies into a stage (single thread)
    auto issue = [&](int row, int stage) {
        const long astart = (long)row * S_STRIDE - c;   // 16B-aligned word index
        mbar_expect_tx(bar_u[stage], NARR * SEG_COPY_BYTES);
#pragma unroll
        for (int a = 0; a < NARR; a++) {
            const uint32_t dst = smem_base + (uint32_t)(stage * STAGE_WORDS
                                                        + a * SEG_ALLOC_WORDS) * 4u;
            bulk_copy(dst, arrs[a] + astart, SEG_COPY_BYTES, bar_u[stage]);
        }
    };

    if (t == 0) {
        issue(bid, 0);
        if (bid + GRID < NROWS) issue(bid + GRID, 1);
    }

    double acc = 0.0;
    int ph[2] = { 0, 0 };
    int stage = 0, buf = 0;
    int row = bid;

    while (row < NROWS) {
        const int next2 = row + 2 * GRID;

        mbar_wait(bar_u[stage], ph[stage]);
        ph[stage] ^= 1;

        const float* S0 = smem + stage * STAGE_WORDS;
        const float* aQ = S0;
        const float* aR = S0 + 1 * SEG_ALLOC_WORDS;
        const float* aE = S0 + 2 * SEG_ALLOC_WORDS;
        const float* aT = S0 + 3 * SEG_ALLOC_WORDS;
        const float* aP = S0 + 4 * SEG_ALLOC_WORDS;
        const float* aB = S0 + 5 * SEG_ALLOC_WORDS;

        // ---- consume stage: ALL smem reads happen before the barrier below
        const float4 q4 = lds_shift(aQ, c,     j0);
        const float4 rv = lds_shift(aR, c + 1, j0);
        const float4 ev = lds_shift(aE, c + 2, j0);
        const float4 tq = lds_shift(aT, c + 2, j0);
        const float4 pt = lds_shift(aP, c + 2, j0);
        const float4 pb = lds_shift(aB, c + 2, j0);
        const float initv = aQ[c + T_LEN];          // broadcast

        // build affine maps (identity for j==1023)
        const float PT[4] = {pt.x, pt.y, pt.z, pt.w};
        const float PB[4] = {pb.x, pb.y, pb.z, pb.w};
        const float RV[4] = {rv.x, rv.y, rv.z, rv.w};
        const float EV[4] = {ev.x, ev.y, ev.z, ev.w};
        const float TQ[4] = {tq.x, tq.y, tq.z, tq.w};
        const float QV[4] = {q4.x, q4.y, q4.z, q4.w};
        Aff loc[4];
#pragma unroll
        for (int k = 0; k < 4; k++) {
            if (j0 + k < T_LEN - 1) {
                const float cc = fminf(fmaxf(__fdividef(PT[k], PB[k]), EPS_F), 1.0f);
                loc[k].b = GAMMA_F * cc;
                loc[k].a = fmaf(GAMMA_F, EV[k], RV[k]) - loc[k].b * TQ[k];
            } else {
                loc[k].a = 0.0f; loc[k].b = 1.0f;
            }
        }

        // serial suffix composition within thread
        Aff suf[4];
        suf[3] = loc[3];
#pragma unroll
        for (int k = 2; k >= 0; k--) suf[k] = comp(loc[k], suf[k + 1]);

        // one warp-level inclusive suffix scan of thread aggregates
        Aff v = suf[0];
#pragma unroll
        for (int off = 1; off < 32; off <<= 1) {
            const float oa = __shfl_down_sync(0xffffffffu, v.a, off);
            const float ob = __shfl_down_sync(0xffffffffu, v.b, off);
            if (lane + off < 32) { Aff g; g.a = oa; g.b = ob; v = comp(v, g); }
        }

        // in-warp EXCLUSIVE suffix (threads lane+1..31)
        const float ea = __shfl_down_sync(0xffffffffu, v.a, 1);
        const float eb = __shfl_down_sync(0xffffffffu, v.b, 1);
        Aff inwexcl;
        if (lane == 31) { inwexcl.a = 0.0f; inwexcl.b = 1.0f; }
        else            { inwexcl.a = ea;   inwexcl.b = eb;   }

        // publish warp totals (double-buffered), ONE barrier
        if (lane == 0) { swA[buf][w] = v.a; swB[buf][w] = v.b; }
        __syncthreads();

        // stage fully consumed -> refill it for row+2*GRID (overlaps epilogue)
        if (t == 0 && next2 < NROWS) issue(next2, stage);

        // redundant per-thread composition of later warps
        Aff W; W.a = 0.0f; W.b = 1.0f;
        for (int ww = 7; ww > w; ww--) {
            Aff tot; tot.a = swA[buf][ww]; tot.b = swB[buf][ww];
            W = comp(tot, W);
        }
        const Aff S = comp(inwexcl, W);

        // epilogue: apply composed maps, accumulate squared error
        float fsum = 0.0f;
#pragma unroll
        for (int k = 0; k < 4; k++) {
            const Aff m = comp(suf[k], S);
            const float y = fmaf(m.b, initv, m.a);
            const float d = QV[k] - y;
            fsum = fmaf(d, d, fsum);
        }
        acc += (double)fsum;

        buf ^= 1;
        stage ^= 1;
        row += GRID;
    }

    // ---- final: block-reduce per-thread doubles, one arrival per CTA
#pragma unroll
    for (int off = 16; off > 0; off >>= 1)
        acc += __shfl_down_sync(0xffffffffu, acc, off);
    if (lane == 0) ssum[w] = acc;
    __syncthreads();

    if (t == 0) {
        double x = 0.0;
#pragma unroll
        for (int i = 0; i < 8; i++) x += ssum[i];
        __stcg(&g_part[bid], x);
        __threadfence();
        const unsigned old = atomicInc(&g_cnt, GRID - 1);  // wraps after GRID arrivals
        s_last = (old == GRID - 1);
    }
    __syncthreads();

    // ---- very last CTA reduces all partials and writes output
    if (s_last) {
        double x = 0.0;
        for (int i = t; i < GRID; i += NTHREADS)
            x += __ldcg(&g_part[i]);
#pragma unroll
        for (int off = 16; off > 0; off >>= 1)
            x += __shfl_down_sync(0xffffffffu, x, off);
        __shared__ double fs2[8];
        if (lane == 0) fs2[w] = x;
        __syncthreads();
        if (t == 0) {
            double tot = 0.0;
#pragma unroll
            for (int i = 0; i < 8; i++) tot += fs2[i];
            out[0] = (float)(tot / (double)((long long)NROWS * T_LEN));
        }
    }
}

extern "C" void kernel_launch(void* const* d_in, const int* in_sizes, int n_in,
                              void* d_out, int out_size)
{
    const float* Q   = (const float*)d_in[0];
    const float* eQ  = (const float*)d_in[1];
    const float* tQ  = (const float*)d_in[2];
    const float* r   = (const float*)d_in[3];
    const float* tp  = (const float*)d_in[4];
    const float* bp  = (const float*)d_in[5];
    float* out = (float*)d_out;

    static bool attr_set = false;
    if (!attr_set) {
        cudaFuncSetAttribute(retrace_kernel,
                             cudaFuncAttributeMaxDynamicSharedMemorySize, SMEM_BYTES);
        attr_set = true;
    }
    retrace_kernel<<<GRID, NTHREADS, SMEM_BYTES>>>(Q, eQ, tQ, r, tp, bp, out);
}